// round 16
// baseline (speedup 1.0000x reference)
#include <cuda_runtime.h>
#include <cuda_fp16.h>
#include <math_constants.h>
#include <cstdint>

// Quantizer_33036888441545 — VQ argmin via hh-screen + exact 3xfp16 refine.
// R14: pass1 8 math warps x (64x32) tiles — LDS traffic 256->192KB/tile, tensor-bound.

#define DDIM 128
#define MAXB 65536
#define MAXC 4096
#define NSEG_P1 2
#define NSEG_RF 8
#define TPB_P1 320
#define TPB_RF 192

__device__ __half    g_xh[MAXB * DDIM];
__device__ __half    g_ch[MAXC * DDIM];
__device__ __half    g_cl[MAXC * DDIM];
__device__ float     g_cnorm[MAXC];
__device__ float     g_xhn[MAXB];
__device__ float     g_xln[MAXB];
__device__ unsigned  g_clmax;
__device__ unsigned  g_chmax;
__device__ int       g_idx[MAXB];
__device__ int       g_undec[MAXB];
__device__ int       g_count;
__device__ float     g_p1v1[NSEG_P1 * MAXB];
__device__ float     g_p1v2[NSEG_P1 * MAXB];
__device__ int       g_p1i1[NSEG_P1 * MAXB];
__device__ float     g_rv[NSEG_RF * MAXB];
__device__ int       g_ri[NSEG_RF * MAXB];
__device__ float     g_block_loss[1024];

// ---- pass1 smem map (BM=128, 3 full-K slots) ----
#define P1_AH    0          // 32KB A-hi frags
#define P1_SLOT  32768      // 3 x 32KB B slots
#define P1_MB    131072     // full[3] @+0..16 ; empty[3] @+24..40
#define P1_M1    131136     // float [4][128]
#define P1_M2    133184
#define P1_I1    135232
#define SMEM_P1  137280

// ---- refine smem map (BM=64, unchanged) ----
#define RF_AH    0
#define RF_AL    16384
#define RF_SLOT  32768
#define RF_MB    65536
#define RF_BV    65600
#define RF_BI    66112
#define RF_LIST  66624
#define SMEM_RF  66880

// ============ helpers ============
__device__ __forceinline__ uint32_t smem_u32(const void* p) {
    uint32_t a;
    asm("{ .reg .u64 t; cvta.to.shared.u64 t, %1; cvt.u32.u64 %0, t; }" : "=r"(a) : "l"(p));
    return a;
}
__device__ __forceinline__ void mbar_init(uint32_t a, uint32_t cnt) {
    asm volatile("mbarrier.init.shared.b64 [%0], %1;" :: "r"(a), "r"(cnt) : "memory");
}
__device__ __forceinline__ void mbar_arrive(uint32_t a) {
    asm volatile("mbarrier.arrive.shared.b64 _, [%0];" :: "r"(a) : "memory");
}
__device__ __forceinline__ void mbar_wait(uint32_t a, uint32_t parity) {
    uint32_t done = 0;
    while (!done) {
        asm volatile(
            "{ .reg .pred p; mbarrier.try_wait.parity.acquire.cta.shared::cta.b64 p, [%1], %2, 0x989680; selp.b32 %0,1,0,p; }"
            : "=r"(done) : "r"(a), "r"(parity) : "memory");
    }
}
__device__ __forceinline__ void cp16(uint32_t dst, const float* src) {
    asm volatile("cp.async.cg.shared.global [%0], [%1], 16;" :: "r"(dst), "l"(src) : "memory");
}
__device__ __forceinline__ void cp_commit() { asm volatile("cp.async.commit_group;" ::: "memory"); }
__device__ __forceinline__ void cp_wait0()  { asm volatile("cp.async.wait_group 0;"  ::: "memory"); }

__device__ __forceinline__ void mma16(float* c, const uint4& a, const uint2& b) {
    asm volatile(
        "mma.sync.aligned.m16n8k16.row.col.f32.f16.f16.f32 "
        "{%0,%1,%2,%3}, {%4,%5,%6,%7}, {%8,%9}, {%0,%1,%2,%3};"
        : "+f"(c[0]), "+f"(c[1]), "+f"(c[2]), "+f"(c[3])
        : "r"(a.x), "r"(a.y), "r"(a.z), "r"(a.w), "r"(b.x), "r"(b.y));
}

// A-frag half2-unit index, 64-row block (refine), row mloc (0..63), even k.
__device__ __forceinline__ int a_frag_h2_64(int mloc, int k) {
    int ks = k >> 4, kk = k & 15, ma = mloc >> 4, r = mloc & 15;
    int lane = (r & 7) * 4 + ((kk & 7) >> 1);
    int reg  = ((kk >> 3) << 1) | (r >> 3);
    return ((ks * 4 + ma) * 32 + lane) * 4 + reg;
}
// A-frag half2-unit index, 128-row block (pass1), row mloc (0..127), even k.
__device__ __forceinline__ int a_frag_h2_128(int mloc, int k) {
    int ks = k >> 4, kk = k & 15, ma = mloc >> 4, r = mloc & 15;
    int lane = (r & 7) * 4 + ((kk & 7) >> 1);
    int reg  = ((kk >> 3) << 1) | (r >> 3);
    return ((ks * 8 + ma) * 32 + lane) * 4 + reg;
}

// ============ split_x: smem-staged coalesced frag output ============
__global__ void split_x(const float* __restrict__ x)
{
    if (blockIdx.x == 0 && threadIdx.x == 0) { g_count = 0; g_clmax = 0u; g_chmax = 0u; }
    __shared__ __half2 stage[8192];
    const int tid = threadIdx.x, wid = tid >> 5, lane = tid & 31;
    const int blk = blockIdx.x;

#pragma unroll 4
    for (int it = 0; it < 16; it++) {
        int mloc = wid * 16 + it;
        int row = blk * 128 + mloc;
        float4 v = reinterpret_cast<const float4*>(x)[(size_t)row * 32 + lane];
        float vv[4] = {v.x, v.y, v.z, v.w};
        __half h[4];
        float hs = 0.0f, ls = 0.0f;
#pragma unroll
        for (int j = 0; j < 4; j++) {
            h[j] = __float2half_rn(vv[j]);
            float hf = __half2float(h[j]);
            float l = vv[j] - hf;
            hs = fmaf(hf, hf, hs);
            ls = fmaf(l, l, ls);
        }
        int u = a_frag_h2_128(mloc, lane * 4);
        stage[u]     = __halves2half2(h[0], h[1]);
        stage[u + 4] = __halves2half2(h[2], h[3]);
#pragma unroll
        for (int o = 16; o; o >>= 1) {
            hs += __shfl_xor_sync(0xffffffffu, hs, o);
            ls += __shfl_xor_sync(0xffffffffu, ls, o);
        }
        if (lane == 0) { g_xhn[row] = sqrtf(hs); g_xln[row] = sqrtf(ls); }
    }
    __syncthreads();
    float4* dst = reinterpret_cast<float4*>(g_xh) + (size_t)blk * 2048;
    const float4* src = reinterpret_cast<const float4*>(stage);
    for (int i = tid; i < 2048; i += 256) dst[i] = src[i];
}

// ============ split_c (unchanged) ============
__global__ void split_c(const float* __restrict__ codes)
{
    int n    = blockIdx.x * 8 + (threadIdx.x >> 5);
    int lane = threadIdx.x & 31;
    float4 v = reinterpret_cast<const float4*>(codes)[(size_t)n * 32 + lane];
    float vv[4] = {v.x, v.y, v.z, v.w};
    __half h[4]; float l[4];
    float cs = 0.0f, hs = 0.0f, ls = 0.0f;
#pragma unroll
    for (int j = 0; j < 4; j++) {
        h[j] = __float2half_rn(vv[j]);
        float hf = __half2float(h[j]);
        l[j] = vv[j] - hf;
        cs = fmaf(vv[j], vv[j], cs);
        hs = fmaf(hf, hf, hs);
        ls = fmaf(l[j], l[j], ls);
    }
    int t = n >> 7, nloc = n & 127, na = nloc >> 3;
    __half2* ch2 = reinterpret_cast<__half2*>(g_ch);
    __half2* cl2 = reinterpret_cast<__half2*>(g_cl);
#pragma unroll
    for (int p = 0; p < 2; p++) {
        int k = lane * 4 + p * 2;
        int kc = k >> 5, ks2 = (k >> 4) & 1, kk = k & 15;
        int lane_f = (nloc & 7) * 4 + ((kk & 7) >> 1);
        int reg    = kk >> 3;
        size_t u = ((((size_t)(t * 4 + kc) * 2 + ks2) * 16 + na) * 32 + lane_f) * 2 + reg;
        ch2[u] = __halves2half2(h[p * 2], h[p * 2 + 1]);
        cl2[u] = __halves2half2(__float2half_rn(l[p * 2]), __float2half_rn(l[p * 2 + 1]));
    }
#pragma unroll
    for (int o = 16; o; o >>= 1) {
        cs += __shfl_xor_sync(0xffffffffu, cs, o);
        hs += __shfl_xor_sync(0xffffffffu, hs, o);
        ls += __shfl_xor_sync(0xffffffffu, ls, o);
    }
    if (lane == 0) {
        g_cnorm[n] = cs;
        atomicMax(&g_chmax, __float_as_uint(sqrtf(hs)));
        atomicMax(&g_clmax, __float_as_uint(sqrtf(ls)));
    }
}

// ============ pass1: hh GEMM, 8 math warps (64x32 tiles) + 2 producers ============
__global__ __launch_bounds__(TPB_P1, 1)
void vq_pass1(int C)
{
    extern __shared__ char smem[];
    const uint32_t sb = smem_u32(smem);
    const int tid = threadIdx.x, wid = tid >> 5, lane = tid & 31;
    const int rb  = blockIdx.x >> 1;
    const int seg = blockIdx.x & 1;
    const int row0 = rb * 128;
    const int ntseg = (C >> 7) / NSEG_P1;      // 16 tiles
    const int t0 = seg * ntseg;

    if (tid == 0) {
#pragma unroll
        for (int s = 0; s < 3; s++) {
            mbar_init(sb + P1_MB + s * 8, 64);        // full: 2 producer warps x 32 lanes
            mbar_init(sb + P1_MB + 24 + s * 8, 8);    // empty: 8 math warps
        }
    }
    {   // resident A-hi (32KB)
        const float* srch = reinterpret_cast<const float*>(g_xh) + (size_t)rb * 8192;
        for (int i = tid; i < 2048; i += TPB_P1) cp16(sb + P1_AH + i * 16, srch + i * 4);
        cp_commit(); cp_wait0();
    }
    __syncthreads();

    if (wid < 8) {
        // math warps: 64 rows (wm in {0,1}) x 32 cols (wn in {0..3})
        const int wm = wid >> 2, wn = wid & 3;
        float m1[8], m2[8]; int i1[8];
#pragma unroll
        for (int s = 0; s < 8; s++) { m1[s] = -CUDART_INF_F; m2[s] = -CUDART_INF_F; i1[s] = 0; }
        uint32_t pf[3] = {0, 0, 0};
        float acc[4][4][4];

        for (int tt = 0; tt < ntseg; tt++) {
            const int t = t0 + tt;
            const int slot = tt % 3;
            const uint32_t bbase = (uint32_t)(P1_SLOT + slot * 32768);
            float cnh[8];
            const int cb = t * 128 + wn * 32 + (lane & 3) * 2;
#pragma unroll
            for (int na = 0; na < 4; na++) {
                cnh[na * 2]     = -0.5f * __ldg(&g_cnorm[cb + na * 8]);
                cnh[na * 2 + 1] = -0.5f * __ldg(&g_cnorm[cb + na * 8 + 1]);
            }
#pragma unroll
            for (int ma = 0; ma < 4; ma++)
#pragma unroll
                for (int na = 0; na < 4; na++) {
                    acc[ma][na][0] = cnh[na * 2];
                    acc[ma][na][1] = cnh[na * 2 + 1];
                    acc[ma][na][2] = cnh[na * 2];
                    acc[ma][na][3] = cnh[na * 2 + 1];
                }

            mbar_wait(sb + P1_MB + slot * 8, pf[slot]); pf[slot] ^= 1;
#pragma unroll
            for (int ks = 0; ks < 8; ks++) {
                uint4 af[4]; uint2 bf[4];
#pragma unroll
                for (int ma = 0; ma < 4; ma++)
                    af[ma] = *reinterpret_cast<const uint4*>(
                        smem + P1_AH + (((ks * 8) + wm * 4 + ma) * 32 + lane) * 16);
#pragma unroll
                for (int na = 0; na < 4; na++)
                    bf[na] = *reinterpret_cast<const uint2*>(
                        smem + bbase + (((ks * 16) + wn * 4 + na) * 32 + lane) * 8);
#pragma unroll
                for (int ma = 0; ma < 4; ma++)
#pragma unroll
                    for (int na = 0; na < 4; na++)
                        mma16(acc[ma][na], af[ma], bf[na]);
            }
            if (lane == 0) mbar_arrive(sb + P1_MB + 24 + slot * 8);

            // branchless top-2 (max domain); ties keep first index
#pragma unroll
            for (int ma = 0; ma < 4; ma++) {
                const int slo = ma * 2, shi = ma * 2 + 1;
#pragma unroll
                for (int na = 0; na < 4; na++) {
                    const int c0 = t * 128 + wn * 32 + na * 8 + (lane & 3) * 2;
                    float a00 = acc[ma][na][0], a01 = acc[ma][na][1];
                    float a10 = acc[ma][na][2], a11 = acc[ma][na][3];
                    m2[slo] = fmaxf(m2[slo], fminf(a00, m1[slo]));
                    i1[slo] = (a00 > m1[slo]) ? c0 : i1[slo];
                    m1[slo] = fmaxf(m1[slo], a00);
                    m2[slo] = fmaxf(m2[slo], fminf(a01, m1[slo]));
                    i1[slo] = (a01 > m1[slo]) ? (c0 + 1) : i1[slo];
                    m1[slo] = fmaxf(m1[slo], a01);
                    m2[shi] = fmaxf(m2[shi], fminf(a10, m1[shi]));
                    i1[shi] = (a10 > m1[shi]) ? c0 : i1[shi];
                    m1[shi] = fmaxf(m1[shi], a10);
                    m2[shi] = fmaxf(m2[shi], fminf(a11, m1[shi]));
                    i1[shi] = (a11 > m1[shi]) ? (c0 + 1) : i1[shi];
                    m1[shi] = fmaxf(m1[shi], a11);
                }
            }
        }
        // lane merge (4 lanes per row), then stash per wn stripe
#pragma unroll
        for (int s = 0; s < 8; s++) {
            float v1 = m1[s], v2 = m2[s]; int ii = i1[s];
#pragma unroll
            for (int o = 1; o <= 2; o <<= 1) {
                float a1 = __shfl_xor_sync(0xffffffffu, v1, o);
                float a2 = __shfl_xor_sync(0xffffffffu, v2, o);
                int   ai = __shfl_xor_sync(0xffffffffu, ii, o);
                bool bwin = (a1 > v1) || (a1 == v1 && ai < ii);
                float loser1 = bwin ? v1 : a1;
                v2 = fmaxf(fmaxf(v2, a2), loser1);
                v1 = bwin ? a1 : v1;
                ii = bwin ? ai : ii;
            }
            if ((lane & 3) == 0) {
                int row = wm * 64 + (s >> 1) * 16 + (s & 1) * 8 + (lane >> 2);
                reinterpret_cast<float*>(smem + P1_M1)[wn * 128 + row] = v1;
                reinterpret_cast<float*>(smem + P1_M2)[wn * 128 + row] = v2;
                reinterpret_cast<int*>(smem + P1_I1)[wn * 128 + row]   = ii;
            }
        }
    } else {
        // 2 producer warps co-fill full-K slots
        const int pw = wid - 8;
        uint32_t pe[3] = {0, 0, 0};
        for (int tt = 0; tt < ntseg; tt++) {
            const int slot = tt % 3;
            if (tt >= 3) { mbar_wait(sb + P1_MB + 24 + slot * 8, pe[slot]); pe[slot] ^= 1; }
            const float* src = reinterpret_cast<const float*>(g_ch)
                             + ((size_t)(t0 + tt) * 8192) + pw * 4096;
            const uint32_t dst = sb + P1_SLOT + slot * 32768 + pw * 16384;
#pragma unroll
            for (int i = 0; i < 32; i++)
                cp16(dst + (uint32_t)((i * 32 + lane) << 4), src + ((i * 32 + lane) << 2));
            cp_commit(); cp_wait0();
            mbar_arrive(sb + P1_MB + slot * 8);   // 32 lanes x 2 warps -> 64
        }
    }
    __syncthreads();

    if (tid < 128) {
        const float* sm1 = reinterpret_cast<const float*>(smem + P1_M1);
        const float* sm2 = reinterpret_cast<const float*>(smem + P1_M2);
        const int*   si1 = reinterpret_cast<const int*>(smem + P1_I1);
        float v1 = sm1[tid], v2 = sm2[tid]; int ii = si1[tid];
#pragma unroll
        for (int wnn = 1; wnn < 4; wnn++) {
            float b1 = sm1[wnn * 128 + tid], b2 = sm2[wnn * 128 + tid];
            int   bi = si1[wnn * 128 + tid];
            bool bwin = (b1 > v1) || (b1 == v1 && bi < ii);
            float loser1 = bwin ? v1 : b1;
            v2 = fmaxf(fmaxf(v2, b2), loser1);
            v1 = bwin ? b1 : v1;
            ii = bwin ? bi : ii;
        }
        int o = seg * MAXB + row0 + tid;
        g_p1v1[o] = v1; g_p1v2[o] = v2; g_p1i1[o] = ii;
    }
}

// ============ decide: merge segs, threshold; undecided marked -(li+1) in g_idx ============
__global__ void decide_kernel()
{
    int row = blockIdx.x * 256 + threadIdx.x;
    float v1 = g_p1v1[row], v2 = g_p1v2[row]; int ii = g_p1i1[row];
    float b1 = g_p1v1[MAXB + row], b2 = g_p1v2[MAXB + row]; int bi = g_p1i1[MAXB + row];
    bool bwin = b1 > v1;
    float loser1 = bwin ? v1 : b1;
    float m2f = fmaxf(fmaxf(v2, b2), loser1);
    float m1f = bwin ? b1 : v1;
    int   idx = bwin ? bi : ii;
    float xhn = g_xhn[row], xln = g_xln[row];
    float clm = __uint_as_float(g_clmax), chm = __uint_as_float(g_chmax);
    float eb = xhn * clm + xln * chm + xln * clm;
    float thr = 4.0f * eb + 0.03125f;
    float gap = 2.0f * (m1f - m2f);
    if (gap > thr) {
        g_idx[row] = idx;
    } else {
        int p = atomicAdd(&g_count, 1);
        g_undec[p] = row;
        g_idx[row] = -(p + 1);
    }
}

// ============ refine: exact 3-pass, C split into NSEG_RF segments (unchanged) ============
__global__ __launch_bounds__(TPB_RF, 2)
void vq_refine(const float* __restrict__ x, int C)
{
    const int cnt = *(volatile int*)&g_count;
    const int rg  = blockIdx.x >> 3;
    const int seg = blockIdx.x & 7;
    if (rg * 64 >= cnt) return;

    extern __shared__ char smem[];
    const uint32_t sb = smem_u32(smem);
    const int tid = threadIdx.x, wid = tid >> 5, lane = tid & 31;
    const int ntseg = (C >> 7) / NSEG_RF;
    const int t0 = seg * ntseg;

    if (tid == 0) {
#pragma unroll
        for (int s = 0; s < 4; s++) {
            mbar_init(sb + RF_MB + s * 8, 32);
            mbar_init(sb + RF_MB + 32 + s * 8, 4);
        }
    }
    int* list = reinterpret_cast<int*>(smem + RF_LIST);
    if (tid < 64) {
        int li = rg * 64 + tid;
        list[tid] = g_undec[(li < cnt) ? li : (cnt - 1)];
    }
    __syncthreads();
    if (tid < 128) {
        int r_loc = tid >> 1, half = tid & 1;
        int r = list[r_loc];
        const float4* xp = reinterpret_cast<const float4*>(x + (size_t)r * DDIM) + half * 16;
        __half2* ah = reinterpret_cast<__half2*>(smem + RF_AH);
        __half2* al = reinterpret_cast<__half2*>(smem + RF_AL);
#pragma unroll 4
        for (int qq = 0; qq < 16; qq++) {
            int q = half * 16 + qq;
            float4 v = xp[qq];
            float vv[4] = {v.x, v.y, v.z, v.w};
            __half h[4]; __half l[4];
#pragma unroll
            for (int j = 0; j < 4; j++) {
                h[j] = __float2half_rn(vv[j]);
                l[j] = __float2half_rn(vv[j] - __half2float(h[j]));
            }
#pragma unroll
            for (int p = 0; p < 2; p++) {
                int k = q * 4 + p * 2;
                int u = a_frag_h2_64(r_loc, k);
                ah[u] = __halves2half2(h[p * 2], h[p * 2 + 1]);
                al[u] = __halves2half2(l[p * 2], l[p * 2 + 1]);
            }
        }
    }
    __syncthreads();

    if (wid < 4) {
        const int wm = wid >> 1, wn = wid & 1;
        float acc[2][8][4];
#pragma unroll
        for (int a = 0; a < 2; a++)
#pragma unroll
            for (int b = 0; b < 8; b++)
#pragma unroll
                for (int r = 0; r < 4; r++) acc[a][b][r] = 0.0f;
        float bestv[4]; int besti[4];
#pragma unroll
        for (int s = 0; s < 4; s++) { bestv[s] = CUDART_INF_F; besti[s] = 0; }
        uint32_t pf[4] = {0, 0, 0, 0};

        for (int tt = 0; tt < ntseg; tt++) {
            const int t = t0 + tt;
            float cn[16];
            const int cb = t * 128 + wn * 64 + (lane & 3) * 2;
#pragma unroll
            for (int na = 0; na < 8; na++) {
                cn[na * 2]     = __ldg(&g_cnorm[cb + na * 8]);
                cn[na * 2 + 1] = __ldg(&g_cnorm[cb + na * 8 + 1]);
            }
#pragma unroll 1
            for (int kc = 0; kc < 4; kc++) {
                const int sch = (kc * 2) & 3, scl = sch + 1;
                const uint32_t bch = (uint32_t)(RF_SLOT + (sch << 13));
                const uint32_t bcl = (uint32_t)(RF_SLOT + (scl << 13));
                mbar_wait(sb + RF_MB + sch * 8, pf[sch]); pf[sch] ^= 1;
#pragma unroll
                for (int pass = 0; pass < 2; pass++) {
                    const uint32_t abase = pass ? RF_AL : RF_AH;
#pragma unroll
                    for (int ks2 = 0; ks2 < 2; ks2++) {
                        const int ks = kc * 2 + ks2;
                        uint4 af[2]; uint2 bf[8];
#pragma unroll
                        for (int ma = 0; ma < 2; ma++)
                            af[ma] = *reinterpret_cast<const uint4*>(
                                smem + abase + (((ks * 4) + wm * 2 + ma) * 32 + lane) * 16);
#pragma unroll
                        for (int na = 0; na < 8; na++)
                            bf[na] = *reinterpret_cast<const uint2*>(
                                smem + bch + (((ks2 * 16) + wn * 8 + na) * 32 + lane) * 8);
#pragma unroll
                        for (int ma = 0; ma < 2; ma++)
#pragma unroll
                            for (int na = 0; na < 8; na++)
                                mma16(acc[ma][na], af[ma], bf[na]);
                    }
                }
                if (lane == 0) mbar_arrive(sb + RF_MB + 32 + sch * 8);

                mbar_wait(sb + RF_MB + scl * 8, pf[scl]); pf[scl] ^= 1;
#pragma unroll
                for (int ks2 = 0; ks2 < 2; ks2++) {
                    const int ks = kc * 2 + ks2;
                    uint4 af[2]; uint2 bf[8];
#pragma unroll
                    for (int ma = 0; ma < 2; ma++)
                        af[ma] = *reinterpret_cast<const uint4*>(
                            smem + RF_AH + (((ks * 4) + wm * 2 + ma) * 32 + lane) * 16);
#pragma unroll
                    for (int na = 0; na < 8; na++)
                        bf[na] = *reinterpret_cast<const uint2*>(
                            smem + bcl + (((ks2 * 16) + wn * 8 + na) * 32 + lane) * 8);
#pragma unroll
                    for (int ma = 0; ma < 2; ma++)
#pragma unroll
                        for (int na = 0; na < 8; na++)
                            mma16(acc[ma][na], af[ma], bf[na]);
                }
                if (lane == 0) mbar_arrive(sb + RF_MB + 32 + scl * 8);
            }
#pragma unroll
            for (int ma = 0; ma < 2; ma++) {
                const int slo = ma * 2, shi = ma * 2 + 1;
#pragma unroll
                for (int na = 0; na < 8; na++) {
                    const int c0 = t * 128 + wn * 64 + na * 8 + (lane & 3) * 2;
                    float k00 = fmaf(-2.0f, acc[ma][na][0], cn[na * 2]);
                    float k01 = fmaf(-2.0f, acc[ma][na][1], cn[na * 2 + 1]);
                    float k10 = fmaf(-2.0f, acc[ma][na][2], cn[na * 2]);
                    float k11 = fmaf(-2.0f, acc[ma][na][3], cn[na * 2 + 1]);
                    if (k00 < bestv[slo]) { bestv[slo] = k00; besti[slo] = c0; }
                    if (k01 < bestv[slo]) { bestv[slo] = k01; besti[slo] = c0 + 1; }
                    if (k10 < bestv[shi]) { bestv[shi] = k10; besti[shi] = c0; }
                    if (k11 < bestv[shi]) { bestv[shi] = k11; besti[shi] = c0 + 1; }
                    acc[ma][na][0] = 0.0f; acc[ma][na][1] = 0.0f;
                    acc[ma][na][2] = 0.0f; acc[ma][na][3] = 0.0f;
                }
            }
        }
#pragma unroll
        for (int s = 0; s < 4; s++) {
            float v = bestv[s]; int bi = besti[s];
#pragma unroll
            for (int o = 1; o <= 2; o <<= 1) {
                float vo = __shfl_xor_sync(0xffffffffu, v, o);
                int   io = __shfl_xor_sync(0xffffffffu, bi, o);
                if (vo < v || (vo == v && io < bi)) { v = vo; bi = io; }
            }
            if ((lane & 3) == 0) {
                int row = wm * 32 + (s >> 1) * 16 + (s & 1) * 8 + (lane >> 2);
                reinterpret_cast<float*>(smem + RF_BV)[wn * 64 + row] = v;
                reinterpret_cast<int*>(smem + RF_BI)[wn * 64 + row]   = bi;
            }
        }
    } else {
        const int pw = wid - 4;
        uint32_t pe[4] = {0, 0, 0, 0};
        const int nchunks = ntseg * 8;
        for (int c = pw; c < nchunks; c += 2) {
            const int slot = c & 3;
            if (c >= 4) { mbar_wait(sb + RF_MB + 32 + slot * 8, pe[slot]); pe[slot] ^= 1; }
            const int t = t0 + (c >> 3), r = c & 7, kc = r >> 1;
            const float* src = reinterpret_cast<const float*>((r & 1) ? g_cl : g_ch)
                             + ((size_t)(t * 4 + kc) << 11);
            const uint32_t dst = sb + RF_SLOT + (slot << 13);
#pragma unroll
            for (int i = 0; i < 16; i++)
                cp16(dst + (uint32_t)((i * 32 + lane) << 4), src + ((i * 32 + lane) << 2));
            cp_commit(); cp_wait0();
            mbar_arrive(sb + RF_MB + slot * 8);
        }
    }
    __syncthreads();

    if (tid < 64) {
        const float* bv = reinterpret_cast<const float*>(smem + RF_BV);
        const int*   bixs = reinterpret_cast<const int*>(smem + RF_BI);
        float v0 = bv[tid], v1 = bv[64 + tid];
        int i0 = bixs[tid], i1v = bixs[64 + tid];
        int bi = (v1 < v0 || (v1 == v0 && i1v < i0)) ? i1v : i0;
        float vv = (v1 < v0 || (v1 == v0 && i1v < i0)) ? v1 : v0;
        int li = rg * 64 + tid;
        g_rv[seg * MAXB + li] = vv;
        g_ri[seg * MAXB + li] = bi;
    }
}

// ============ gather + loss (inline refine-segment merge) ============
__global__ void gather_loss(const float* __restrict__ x, const float* __restrict__ codes,
                            float* __restrict__ out_q, float* __restrict__ out_idx, int write_idx)
{
    const int tid = threadIdx.x, txg = tid & 15, grp = tid >> 4;
    const int base = blockIdx.x * 64;
    float thr_loss = 0.0f;
    for (int rr = grp; rr < 64; rr += 16) {
        int row = base + rr;
        int bi = g_idx[row];
        if (bi < 0) {
            int li = -bi - 1;
            float v = g_rv[li]; bi = g_ri[li];
#pragma unroll
            for (int s = 1; s < NSEG_RF; s++) {
                float vo = g_rv[s * MAXB + li];
                int   io = g_ri[s * MAXB + li];
                if (vo < v) { v = vo; bi = io; }
            }
        }
        if (txg == 0 && write_idx) out_idx[row] = (float)bi;
        const float4* cq = reinterpret_cast<const float4*>(codes + (size_t)bi * DDIM + txg * 8);
        float4 q0 = cq[0], q1 = cq[1];
        float4* od = reinterpret_cast<float4*>(out_q + (size_t)row * DDIM + txg * 8);
        od[0] = q0; od[1] = q1;
        const float4* xp = reinterpret_cast<const float4*>(x + (size_t)row * DDIM + txg * 8);
        float4 x0 = xp[0], x1 = xp[1];
        float d;
        d = x0.x - q0.x; thr_loss = fmaf(d, d, thr_loss);
        d = x0.y - q0.y; thr_loss = fmaf(d, d, thr_loss);
        d = x0.z - q0.z; thr_loss = fmaf(d, d, thr_loss);
        d = x0.w - q0.w; thr_loss = fmaf(d, d, thr_loss);
        d = x1.x - q1.x; thr_loss = fmaf(d, d, thr_loss);
        d = x1.y - q1.y; thr_loss = fmaf(d, d, thr_loss);
        d = x1.z - q1.z; thr_loss = fmaf(d, d, thr_loss);
        d = x1.w - q1.w; thr_loss = fmaf(d, d, thr_loss);
    }
    __shared__ float red[8];
#pragma unroll
    for (int o = 16; o; o >>= 1) thr_loss += __shfl_xor_sync(0xffffffffu, thr_loss, o);
    if ((tid & 31) == 0) red[tid >> 5] = thr_loss;
    __syncthreads();
    if (tid == 0) {
        float s = 0.0f;
#pragma unroll
        for (int w = 0; w < 8; w++) s += red[w];
        g_block_loss[blockIdx.x] = s;
    }
}

__global__ void finalize_kernel(float* __restrict__ out_loss, int nblocks, float invB)
{
    __shared__ float red[256];
    float s = 0.0f;
    for (int i = threadIdx.x; i < nblocks; i += 256) s += g_block_loss[i];
    red[threadIdx.x] = s;
    __syncthreads();
    for (int o = 128; o; o >>= 1) {
        if (threadIdx.x < o) red[threadIdx.x] += red[threadIdx.x + o];
        __syncthreads();
    }
    if (threadIdx.x == 0) *out_loss = 1.25f * red[0] * invB;  // (1 + BETA) * mean ||x-q||^2
}

extern "C" void kernel_launch(void* const* d_in, const int* in_sizes, int n_in,
                              void* d_out, int out_size)
{
    const float* x     = (const float*)d_in[0];
    const float* codes = (const float*)d_in[1];
    const int B = in_sizes[0] / DDIM;
    const int C = in_sizes[1] / DDIM;

    float* out      = (float*)d_out;
    float* out_q    = out;
    float* out_idx  = out + (size_t)B * DDIM;
    float* out_loss = out + (size_t)B * DDIM + B;

    const long long need_idx  = (long long)B * DDIM + B;
    const long long need_loss = need_idx + 1;
    const int write_idx  = ((long long)out_size >= need_idx)  ? 1 : 0;
    const int write_loss = ((long long)out_size >= need_loss) ? 1 : 0;

    (void)cudaFuncSetAttribute(vq_pass1,  cudaFuncAttributeMaxDynamicSharedMemorySize, SMEM_P1);
    (void)cudaFuncSetAttribute(vq_refine, cudaFuncAttributeMaxDynamicSharedMemorySize, SMEM_RF);

    split_x<<<B / 128, 256>>>(x);
    split_c<<<C / 8, 256>>>(codes);
    vq_pass1<<<(B / 128) * NSEG_P1, TPB_P1, SMEM_P1>>>(C);
    decide_kernel<<<B / 256, 256>>>();
    vq_refine<<<(B / 64) * NSEG_RF, TPB_RF, SMEM_RF>>>(x, C);
    gather_loss<<<B / 64, 256>>>(x, codes, out_q, out_idx, write_idx);
    if (write_loss)
        finalize_kernel<<<1, 256>>>(out_loss, B / 64, 1.0f / (float)B);
}

// round 17
// speedup vs baseline: 1.0760x; 1.0760x over previous
#include <cuda_runtime.h>
#include <cuda_fp16.h>
#include <math_constants.h>
#include <cstdint>

// Quantizer_33036888441545 — VQ argmin via hh-screen + exact 3xfp16 refine.
// R17: R13 config (16 math warps 32x32) + 4-slot ring + overlapped prologue.

#define DDIM 128
#define MAXB 65536
#define MAXC 4096
#define NSEG_P1 2
#define NSEG_RF 8
#define TPB_P1 576
#define TPB_RF 192

__device__ __half    g_xh[MAXB * DDIM];
__device__ __half    g_ch[MAXC * DDIM];
__device__ __half    g_cl[MAXC * DDIM];
__device__ float     g_cnorm[MAXC];
__device__ float     g_xhn[MAXB];
__device__ float     g_xln[MAXB];
__device__ unsigned  g_clmax;
__device__ unsigned  g_chmax;
__device__ int       g_idx[MAXB];
__device__ int       g_undec[MAXB];
__device__ int       g_count;
__device__ float     g_p1v1[NSEG_P1 * MAXB];
__device__ float     g_p1v2[NSEG_P1 * MAXB];
__device__ int       g_p1i1[NSEG_P1 * MAXB];
__device__ float     g_rv[NSEG_RF * MAXB];
__device__ int       g_ri[NSEG_RF * MAXB];
__device__ float     g_block_loss[1024];

// ---- pass1 smem map (BM=128, 4 full-K slots) ----
#define P1_AH    0          // 32KB A-hi frags
#define P1_SLOT  32768      // 4 x 32KB B slots
#define P1_MB    163840     // full[4] @+0..31 ; empty[4] @+32..63
#define P1_M1    163904     // float [4][128]
#define P1_M2    165952
#define P1_I1    168000
#define SMEM_P1  170048

// ---- refine smem map (BM=64, unchanged) ----
#define RF_AH    0
#define RF_AL    16384
#define RF_SLOT  32768
#define RF_MB    65536
#define RF_BV    65600
#define RF_BI    66112
#define RF_LIST  66624
#define SMEM_RF  66880

// ============ helpers ============
__device__ __forceinline__ uint32_t smem_u32(const void* p) {
    uint32_t a;
    asm("{ .reg .u64 t; cvta.to.shared.u64 t, %1; cvt.u32.u64 %0, t; }" : "=r"(a) : "l"(p));
    return a;
}
__device__ __forceinline__ void mbar_init(uint32_t a, uint32_t cnt) {
    asm volatile("mbarrier.init.shared.b64 [%0], %1;" :: "r"(a), "r"(cnt) : "memory");
}
__device__ __forceinline__ void mbar_arrive(uint32_t a) {
    asm volatile("mbarrier.arrive.shared.b64 _, [%0];" :: "r"(a) : "memory");
}
__device__ __forceinline__ void mbar_wait(uint32_t a, uint32_t parity) {
    uint32_t done = 0;
    while (!done) {
        asm volatile(
            "{ .reg .pred p; mbarrier.try_wait.parity.acquire.cta.shared::cta.b64 p, [%1], %2, 0x989680; selp.b32 %0,1,0,p; }"
            : "=r"(done) : "r"(a), "r"(parity) : "memory");
    }
}
__device__ __forceinline__ void cp16(uint32_t dst, const float* src) {
    asm volatile("cp.async.cg.shared.global [%0], [%1], 16;" :: "r"(dst), "l"(src) : "memory");
}
__device__ __forceinline__ void cp_commit() { asm volatile("cp.async.commit_group;" ::: "memory"); }
__device__ __forceinline__ void cp_wait0()  { asm volatile("cp.async.wait_group 0;"  ::: "memory"); }

__device__ __forceinline__ void mma16(float* c, const uint4& a, const uint2& b) {
    asm volatile(
        "mma.sync.aligned.m16n8k16.row.col.f32.f16.f16.f32 "
        "{%0,%1,%2,%3}, {%4,%5,%6,%7}, {%8,%9}, {%0,%1,%2,%3};"
        : "+f"(c[0]), "+f"(c[1]), "+f"(c[2]), "+f"(c[3])
        : "r"(a.x), "r"(a.y), "r"(a.z), "r"(a.w), "r"(b.x), "r"(b.y));
}

// A-frag half2-unit index, 64-row block (refine), row mloc (0..63), even k.
__device__ __forceinline__ int a_frag_h2_64(int mloc, int k) {
    int ks = k >> 4, kk = k & 15, ma = mloc >> 4, r = mloc & 15;
    int lane = (r & 7) * 4 + ((kk & 7) >> 1);
    int reg  = ((kk >> 3) << 1) | (r >> 3);
    return ((ks * 4 + ma) * 32 + lane) * 4 + reg;
}
// A-frag half2-unit index, 128-row block (pass1), row mloc (0..127), even k.
__device__ __forceinline__ int a_frag_h2_128(int mloc, int k) {
    int ks = k >> 4, kk = k & 15, ma = mloc >> 4, r = mloc & 15;
    int lane = (r & 7) * 4 + ((kk & 7) >> 1);
    int reg  = ((kk >> 3) << 1) | (r >> 3);
    return ((ks * 8 + ma) * 32 + lane) * 4 + reg;
}

// ============ split_x: smem-staged coalesced frag output ============
__global__ void split_x(const float* __restrict__ x)
{
    if (blockIdx.x == 0 && threadIdx.x == 0) { g_count = 0; g_clmax = 0u; g_chmax = 0u; }
    __shared__ __half2 stage[8192];
    const int tid = threadIdx.x, wid = tid >> 5, lane = tid & 31;
    const int blk = blockIdx.x;

#pragma unroll 4
    for (int it = 0; it < 16; it++) {
        int mloc = wid * 16 + it;
        int row = blk * 128 + mloc;
        float4 v = reinterpret_cast<const float4*>(x)[(size_t)row * 32 + lane];
        float vv[4] = {v.x, v.y, v.z, v.w};
        __half h[4];
        float hs = 0.0f, ls = 0.0f;
#pragma unroll
        for (int j = 0; j < 4; j++) {
            h[j] = __float2half_rn(vv[j]);
            float hf = __half2float(h[j]);
            float l = vv[j] - hf;
            hs = fmaf(hf, hf, hs);
            ls = fmaf(l, l, ls);
        }
        int u = a_frag_h2_128(mloc, lane * 4);
        stage[u]     = __halves2half2(h[0], h[1]);
        stage[u + 4] = __halves2half2(h[2], h[3]);
#pragma unroll
        for (int o = 16; o; o >>= 1) {
            hs += __shfl_xor_sync(0xffffffffu, hs, o);
            ls += __shfl_xor_sync(0xffffffffu, ls, o);
        }
        if (lane == 0) { g_xhn[row] = sqrtf(hs); g_xln[row] = sqrtf(ls); }
    }
    __syncthreads();
    float4* dst = reinterpret_cast<float4*>(g_xh) + (size_t)blk * 2048;
    const float4* src = reinterpret_cast<const float4*>(stage);
    for (int i = tid; i < 2048; i += 256) dst[i] = src[i];
}

// ============ split_c (unchanged) ============
__global__ void split_c(const float* __restrict__ codes)
{
    int n    = blockIdx.x * 8 + (threadIdx.x >> 5);
    int lane = threadIdx.x & 31;
    float4 v = reinterpret_cast<const float4*>(codes)[(size_t)n * 32 + lane];
    float vv[4] = {v.x, v.y, v.z, v.w};
    __half h[4]; float l[4];
    float cs = 0.0f, hs = 0.0f, ls = 0.0f;
#pragma unroll
    for (int j = 0; j < 4; j++) {
        h[j] = __float2half_rn(vv[j]);
        float hf = __half2float(h[j]);
        l[j] = vv[j] - hf;
        cs = fmaf(vv[j], vv[j], cs);
        hs = fmaf(hf, hf, hs);
        ls = fmaf(l[j], l[j], ls);
    }
    int t = n >> 7, nloc = n & 127, na = nloc >> 3;
    __half2* ch2 = reinterpret_cast<__half2*>(g_ch);
    __half2* cl2 = reinterpret_cast<__half2*>(g_cl);
#pragma unroll
    for (int p = 0; p < 2; p++) {
        int k = lane * 4 + p * 2;
        int kc = k >> 5, ks2 = (k >> 4) & 1, kk = k & 15;
        int lane_f = (nloc & 7) * 4 + ((kk & 7) >> 1);
        int reg    = kk >> 3;
        size_t u = ((((size_t)(t * 4 + kc) * 2 + ks2) * 16 + na) * 32 + lane_f) * 2 + reg;
        ch2[u] = __halves2half2(h[p * 2], h[p * 2 + 1]);
        cl2[u] = __halves2half2(__float2half_rn(l[p * 2]), __float2half_rn(l[p * 2 + 1]));
    }
#pragma unroll
    for (int o = 16; o; o >>= 1) {
        cs += __shfl_xor_sync(0xffffffffu, cs, o);
        hs += __shfl_xor_sync(0xffffffffu, hs, o);
        ls += __shfl_xor_sync(0xffffffffu, ls, o);
    }
    if (lane == 0) {
        g_cnorm[n] = cs;
        atomicMax(&g_chmax, __float_as_uint(sqrtf(hs)));
        atomicMax(&g_clmax, __float_as_uint(sqrtf(ls)));
    }
}

// ============ pass1: hh GEMM, 16 math warps (32x32) + 2 producers, 4-slot ring ============
__global__ __launch_bounds__(TPB_P1, 1)
void vq_pass1(int C)
{
    extern __shared__ char smem[];
    const uint32_t sb = smem_u32(smem);
    const int tid = threadIdx.x, wid = tid >> 5, lane = tid & 31;
    const int rb  = blockIdx.x >> 1;
    const int seg = blockIdx.x & 1;
    const int row0 = rb * 128;
    const int ntseg = (C >> 7) / NSEG_P1;      // 16 tiles
    const int t0 = seg * ntseg;

    if (tid == 0) {
#pragma unroll
        for (int s = 0; s < 4; s++) {
            mbar_init(sb + P1_MB + s * 8, 64);        // full: 2 producer warps x 32 lanes
            mbar_init(sb + P1_MB + 32 + s * 8, 16);   // empty: 16 math warps
        }
    }
    __syncthreads();   // mbar visibility; producers start immediately after this

    if (wid < 16) {
        // math warps load resident A themselves (overlaps producer slot fills)
        {
            const float* srch = reinterpret_cast<const float*>(g_xh) + (size_t)rb * 8192;
            for (int i = tid; i < 2048; i += 512) cp16(sb + P1_AH + i * 16, srch + i * 4);
            cp_commit(); cp_wait0();
            asm volatile("bar.sync 1, 512;" ::: "memory");
        }
        const int wm = wid >> 2, wn = wid & 3;
        float m1[4], m2[4]; int i1[4];
#pragma unroll
        for (int s = 0; s < 4; s++) { m1[s] = -CUDART_INF_F; m2[s] = -CUDART_INF_F; i1[s] = 0; }
        uint32_t pf[4] = {0, 0, 0, 0};
        float acc[2][4][4];

        for (int tt = 0; tt < ntseg; tt++) {
            const int t = t0 + tt;
            const int slot = tt & 3;
            const uint32_t bbase = (uint32_t)(P1_SLOT + slot * 32768);
            float cnh[8];
            const int cb = t * 128 + wn * 32 + (lane & 3) * 2;
#pragma unroll
            for (int na = 0; na < 4; na++) {
                cnh[na * 2]     = -0.5f * __ldg(&g_cnorm[cb + na * 8]);
                cnh[na * 2 + 1] = -0.5f * __ldg(&g_cnorm[cb + na * 8 + 1]);
            }
#pragma unroll
            for (int ma = 0; ma < 2; ma++)
#pragma unroll
                for (int na = 0; na < 4; na++) {
                    acc[ma][na][0] = cnh[na * 2];
                    acc[ma][na][1] = cnh[na * 2 + 1];
                    acc[ma][na][2] = cnh[na * 2];
                    acc[ma][na][3] = cnh[na * 2 + 1];
                }

            mbar_wait(sb + P1_MB + slot * 8, pf[slot]); pf[slot] ^= 1;
#pragma unroll
            for (int ks = 0; ks < 8; ks++) {
                uint4 af[2]; uint2 bf[4];
#pragma unroll
                for (int ma = 0; ma < 2; ma++)
                    af[ma] = *reinterpret_cast<const uint4*>(
                        smem + P1_AH + (((ks * 8) + wm * 2 + ma) * 32 + lane) * 16);
#pragma unroll
                for (int na = 0; na < 4; na++)
                    bf[na] = *reinterpret_cast<const uint2*>(
                        smem + bbase + (((ks * 16) + wn * 4 + na) * 32 + lane) * 8);
#pragma unroll
                for (int ma = 0; ma < 2; ma++)
#pragma unroll
                    for (int na = 0; na < 4; na++)
                        mma16(acc[ma][na], af[ma], bf[na]);
            }
            if (lane == 0) mbar_arrive(sb + P1_MB + 32 + slot * 8);

            // branchless top-2 (max domain); ties keep first index
#pragma unroll
            for (int ma = 0; ma < 2; ma++) {
                const int slo = ma * 2, shi = ma * 2 + 1;
#pragma unroll
                for (int na = 0; na < 4; na++) {
                    const int c0 = t * 128 + wn * 32 + na * 8 + (lane & 3) * 2;
                    float a00 = acc[ma][na][0], a01 = acc[ma][na][1];
                    float a10 = acc[ma][na][2], a11 = acc[ma][na][3];
                    m2[slo] = fmaxf(m2[slo], fminf(a00, m1[slo]));
                    i1[slo] = (a00 > m1[slo]) ? c0 : i1[slo];
                    m1[slo] = fmaxf(m1[slo], a00);
                    m2[slo] = fmaxf(m2[slo], fminf(a01, m1[slo]));
                    i1[slo] = (a01 > m1[slo]) ? (c0 + 1) : i1[slo];
                    m1[slo] = fmaxf(m1[slo], a01);
                    m2[shi] = fmaxf(m2[shi], fminf(a10, m1[shi]));
                    i1[shi] = (a10 > m1[shi]) ? c0 : i1[shi];
                    m1[shi] = fmaxf(m1[shi], a10);
                    m2[shi] = fmaxf(m2[shi], fminf(a11, m1[shi]));
                    i1[shi] = (a11 > m1[shi]) ? (c0 + 1) : i1[shi];
                    m1[shi] = fmaxf(m1[shi], a11);
                }
            }
        }
#pragma unroll
        for (int s = 0; s < 4; s++) {
            float v1 = m1[s], v2 = m2[s]; int ii = i1[s];
#pragma unroll
            for (int o = 1; o <= 2; o <<= 1) {
                float a1 = __shfl_xor_sync(0xffffffffu, v1, o);
                float a2 = __shfl_xor_sync(0xffffffffu, v2, o);
                int   ai = __shfl_xor_sync(0xffffffffu, ii, o);
                bool bwin = (a1 > v1) || (a1 == v1 && ai < ii);
                float loser1 = bwin ? v1 : a1;
                v2 = fmaxf(fmaxf(v2, a2), loser1);
                v1 = bwin ? a1 : v1;
                ii = bwin ? ai : ii;
            }
            if ((lane & 3) == 0) {
                int row = wm * 32 + (s >> 1) * 16 + (s & 1) * 8 + (lane >> 2);
                reinterpret_cast<float*>(smem + P1_M1)[wn * 128 + row] = v1;
                reinterpret_cast<float*>(smem + P1_M2)[wn * 128 + row] = v2;
                reinterpret_cast<int*>(smem + P1_I1)[wn * 128 + row]   = ii;
            }
        }
    } else {
        // 2 producer warps co-fill full-K slots (start immediately)
        const int pw = wid - 16;
        uint32_t pe[4] = {0, 0, 0, 0};
        for (int tt = 0; tt < ntseg; tt++) {
            const int slot = tt & 3;
            if (tt >= 4) { mbar_wait(sb + P1_MB + 32 + slot * 8, pe[slot]); pe[slot] ^= 1; }
            const float* src = reinterpret_cast<const float*>(g_ch)
                             + ((size_t)(t0 + tt) * 8192) + pw * 4096;
            const uint32_t dst = sb + P1_SLOT + slot * 32768 + pw * 16384;
#pragma unroll
            for (int i = 0; i < 32; i++)
                cp16(dst + (uint32_t)((i * 32 + lane) << 4), src + ((i * 32 + lane) << 2));
            cp_commit(); cp_wait0();
            mbar_arrive(sb + P1_MB + slot * 8);   // 32 lanes x 2 warps -> 64
        }
    }
    __syncthreads();

    if (tid < 128) {
        const float* sm1 = reinterpret_cast<const float*>(smem + P1_M1);
        const float* sm2 = reinterpret_cast<const float*>(smem + P1_M2);
        const int*   si1 = reinterpret_cast<const int*>(smem + P1_I1);
        float v1 = sm1[tid], v2 = sm2[tid]; int ii = si1[tid];
#pragma unroll
        for (int wnn = 1; wnn < 4; wnn++) {
            float b1 = sm1[wnn * 128 + tid], b2 = sm2[wnn * 128 + tid];
            int   bi = si1[wnn * 128 + tid];
            bool bwin = (b1 > v1) || (b1 == v1 && bi < ii);
            float loser1 = bwin ? v1 : b1;
            v2 = fmaxf(fmaxf(v2, b2), loser1);
            v1 = bwin ? b1 : v1;
            ii = bwin ? bi : ii;
        }
        int o = seg * MAXB + row0 + tid;
        g_p1v1[o] = v1; g_p1v2[o] = v2; g_p1i1[o] = ii;
    }
}

// ============ decide: merge segs, threshold; undecided marked -(li+1) in g_idx ============
__global__ void decide_kernel()
{
    int row = blockIdx.x * 256 + threadIdx.x;
    float v1 = g_p1v1[row], v2 = g_p1v2[row]; int ii = g_p1i1[row];
    float b1 = g_p1v1[MAXB + row], b2 = g_p1v2[MAXB + row]; int bi = g_p1i1[MAXB + row];
    bool bwin = b1 > v1;
    float loser1 = bwin ? v1 : b1;
    float m2f = fmaxf(fmaxf(v2, b2), loser1);
    float m1f = bwin ? b1 : v1;
    int   idx = bwin ? bi : ii;
    float xhn = g_xhn[row], xln = g_xln[row];
    float clm = __uint_as_float(g_clmax), chm = __uint_as_float(g_chmax);
    float eb = xhn * clm + xln * chm + xln * clm;
    float thr = 4.0f * eb + 0.03125f;
    float gap = 2.0f * (m1f - m2f);
    if (gap > thr) {
        g_idx[row] = idx;
    } else {
        int p = atomicAdd(&g_count, 1);
        g_undec[p] = row;
        g_idx[row] = -(p + 1);
    }
}

// ============ refine: exact 3-pass, C split into NSEG_RF segments (unchanged) ============
__global__ __launch_bounds__(TPB_RF, 2)
void vq_refine(const float* __restrict__ x, int C)
{
    const int cnt = *(volatile int*)&g_count;
    const int rg  = blockIdx.x >> 3;
    const int seg = blockIdx.x & 7;
    if (rg * 64 >= cnt) return;

    extern __shared__ char smem[];
    const uint32_t sb = smem_u32(smem);
    const int tid = threadIdx.x, wid = tid >> 5, lane = tid & 31;
    const int ntseg = (C >> 7) / NSEG_RF;
    const int t0 = seg * ntseg;

    if (tid == 0) {
#pragma unroll
        for (int s = 0; s < 4; s++) {
            mbar_init(sb + RF_MB + s * 8, 32);
            mbar_init(sb + RF_MB + 32 + s * 8, 4);
        }
    }
    int* list = reinterpret_cast<int*>(smem + RF_LIST);
    if (tid < 64) {
        int li = rg * 64 + tid;
        list[tid] = g_undec[(li < cnt) ? li : (cnt - 1)];
    }
    __syncthreads();
    if (tid < 128) {
        int r_loc = tid >> 1, half = tid & 1;
        int r = list[r_loc];
        const float4* xp = reinterpret_cast<const float4*>(x + (size_t)r * DDIM) + half * 16;
        __half2* ah = reinterpret_cast<__half2*>(smem + RF_AH);
        __half2* al = reinterpret_cast<__half2*>(smem + RF_AL);
#pragma unroll 4
        for (int qq = 0; qq < 16; qq++) {
            int q = half * 16 + qq;
            float4 v = xp[qq];
            float vv[4] = {v.x, v.y, v.z, v.w};
            __half h[4]; __half l[4];
#pragma unroll
            for (int j = 0; j < 4; j++) {
                h[j] = __float2half_rn(vv[j]);
                l[j] = __float2half_rn(vv[j] - __half2float(h[j]));
            }
#pragma unroll
            for (int p = 0; p < 2; p++) {
                int k = q * 4 + p * 2;
                int u = a_frag_h2_64(r_loc, k);
                ah[u] = __halves2half2(h[p * 2], h[p * 2 + 1]);
                al[u] = __halves2half2(l[p * 2], l[p * 2 + 1]);
            }
        }
    }
    __syncthreads();

    if (wid < 4) {
        const int wm = wid >> 1, wn = wid & 1;
        float acc[2][8][4];
#pragma unroll
        for (int a = 0; a < 2; a++)
#pragma unroll
            for (int b = 0; b < 8; b++)
#pragma unroll
                for (int r = 0; r < 4; r++) acc[a][b][r] = 0.0f;
        float bestv[4]; int besti[4];
#pragma unroll
        for (int s = 0; s < 4; s++) { bestv[s] = CUDART_INF_F; besti[s] = 0; }
        uint32_t pf[4] = {0, 0, 0, 0};

        for (int tt = 0; tt < ntseg; tt++) {
            const int t = t0 + tt;
            float cn[16];
            const int cb = t * 128 + wn * 64 + (lane & 3) * 2;
#pragma unroll
            for (int na = 0; na < 8; na++) {
                cn[na * 2]     = __ldg(&g_cnorm[cb + na * 8]);
                cn[na * 2 + 1] = __ldg(&g_cnorm[cb + na * 8 + 1]);
            }
#pragma unroll 1
            for (int kc = 0; kc < 4; kc++) {
                const int sch = (kc * 2) & 3, scl = sch + 1;
                const uint32_t bch = (uint32_t)(RF_SLOT + (sch << 13));
                const uint32_t bcl = (uint32_t)(RF_SLOT + (scl << 13));
                mbar_wait(sb + RF_MB + sch * 8, pf[sch]); pf[sch] ^= 1;
#pragma unroll
                for (int pass = 0; pass < 2; pass++) {
                    const uint32_t abase = pass ? RF_AL : RF_AH;
#pragma unroll
                    for (int ks2 = 0; ks2 < 2; ks2++) {
                        const int ks = kc * 2 + ks2;
                        uint4 af[2]; uint2 bf[8];
#pragma unroll
                        for (int ma = 0; ma < 2; ma++)
                            af[ma] = *reinterpret_cast<const uint4*>(
                                smem + abase + (((ks * 4) + wm * 2 + ma) * 32 + lane) * 16);
#pragma unroll
                        for (int na = 0; na < 8; na++)
                            bf[na] = *reinterpret_cast<const uint2*>(
                                smem + bch + (((ks2 * 16) + wn * 8 + na) * 32 + lane) * 8);
#pragma unroll
                        for (int ma = 0; ma < 2; ma++)
#pragma unroll
                            for (int na = 0; na < 8; na++)
                                mma16(acc[ma][na], af[ma], bf[na]);
                    }
                }
                if (lane == 0) mbar_arrive(sb + RF_MB + 32 + sch * 8);

                mbar_wait(sb + RF_MB + scl * 8, pf[scl]); pf[scl] ^= 1;
#pragma unroll
                for (int ks2 = 0; ks2 < 2; ks2++) {
                    const int ks = kc * 2 + ks2;
                    uint4 af[2]; uint2 bf[8];
#pragma unroll
                    for (int ma = 0; ma < 2; ma++)
                        af[ma] = *reinterpret_cast<const uint4*>(
                            smem + RF_AH + (((ks * 4) + wm * 2 + ma) * 32 + lane) * 16);
#pragma unroll
                    for (int na = 0; na < 8; na++)
                        bf[na] = *reinterpret_cast<const uint2*>(
                            smem + bcl + (((ks2 * 16) + wn * 8 + na) * 32 + lane) * 8);
#pragma unroll
                    for (int ma = 0; ma < 2; ma++)
#pragma unroll
                        for (int na = 0; na < 8; na++)
                            mma16(acc[ma][na], af[ma], bf[na]);
                }
                if (lane == 0) mbar_arrive(sb + RF_MB + 32 + scl * 8);
            }
#pragma unroll
            for (int ma = 0; ma < 2; ma++) {
                const int slo = ma * 2, shi = ma * 2 + 1;
#pragma unroll
                for (int na = 0; na < 8; na++) {
                    const int c0 = t * 128 + wn * 64 + na * 8 + (lane & 3) * 2;
                    float k00 = fmaf(-2.0f, acc[ma][na][0], cn[na * 2]);
                    float k01 = fmaf(-2.0f, acc[ma][na][1], cn[na * 2 + 1]);
                    float k10 = fmaf(-2.0f, acc[ma][na][2], cn[na * 2]);
                    float k11 = fmaf(-2.0f, acc[ma][na][3], cn[na * 2 + 1]);
                    if (k00 < bestv[slo]) { bestv[slo] = k00; besti[slo] = c0; }
                    if (k01 < bestv[slo]) { bestv[slo] = k01; besti[slo] = c0 + 1; }
                    if (k10 < bestv[shi]) { bestv[shi] = k10; besti[shi] = c0; }
                    if (k11 < bestv[shi]) { bestv[shi] = k11; besti[shi] = c0 + 1; }
                    acc[ma][na][0] = 0.0f; acc[ma][na][1] = 0.0f;
                    acc[ma][na][2] = 0.0f; acc[ma][na][3] = 0.0f;
                }
            }
        }
#pragma unroll
        for (int s = 0; s < 4; s++) {
            float v = bestv[s]; int bi = besti[s];
#pragma unroll
            for (int o = 1; o <= 2; o <<= 1) {
                float vo = __shfl_xor_sync(0xffffffffu, v, o);
                int   io = __shfl_xor_sync(0xffffffffu, bi, o);
                if (vo < v || (vo == v && io < bi)) { v = vo; bi = io; }
            }
            if ((lane & 3) == 0) {
                int row = wm * 32 + (s >> 1) * 16 + (s & 1) * 8 + (lane >> 2);
                reinterpret_cast<float*>(smem + RF_BV)[wn * 64 + row] = v;
                reinterpret_cast<int*>(smem + RF_BI)[wn * 64 + row]   = bi;
            }
        }
    } else {
        const int pw = wid - 4;
        uint32_t pe[4] = {0, 0, 0, 0};
        const int nchunks = ntseg * 8;
        for (int c = pw; c < nchunks; c += 2) {
            const int slot = c & 3;
            if (c >= 4) { mbar_wait(sb + RF_MB + 32 + slot * 8, pe[slot]); pe[slot] ^= 1; }
            const int t = t0 + (c >> 3), r = c & 7, kc = r >> 1;
            const float* src = reinterpret_cast<const float*>((r & 1) ? g_cl : g_ch)
                             + ((size_t)(t * 4 + kc) << 11);
            const uint32_t dst = sb + RF_SLOT + (slot << 13);
#pragma unroll
            for (int i = 0; i < 16; i++)
                cp16(dst + (uint32_t)((i * 32 + lane) << 4), src + ((i * 32 + lane) << 2));
            cp_commit(); cp_wait0();
            mbar_arrive(sb + RF_MB + slot * 8);
        }
    }
    __syncthreads();

    if (tid < 64) {
        const float* bv = reinterpret_cast<const float*>(smem + RF_BV);
        const int*   bixs = reinterpret_cast<const int*>(smem + RF_BI);
        float v0 = bv[tid], v1 = bv[64 + tid];
        int i0 = bixs[tid], i1v = bixs[64 + tid];
        int bi = (v1 < v0 || (v1 == v0 && i1v < i0)) ? i1v : i0;
        float vv = (v1 < v0 || (v1 == v0 && i1v < i0)) ? v1 : v0;
        int li = rg * 64 + tid;
        g_rv[seg * MAXB + li] = vv;
        g_ri[seg * MAXB + li] = bi;
    }
}

// ============ gather + loss (inline refine-segment merge) ============
__global__ void gather_loss(const float* __restrict__ x, const float* __restrict__ codes,
                            float* __restrict__ out_q, float* __restrict__ out_idx, int write_idx)
{
    const int tid = threadIdx.x, txg = tid & 15, grp = tid >> 4;
    const int base = blockIdx.x * 64;
    float thr_loss = 0.0f;
    for (int rr = grp; rr < 64; rr += 16) {
        int row = base + rr;
        int bi = g_idx[row];
        if (bi < 0) {
            int li = -bi - 1;
            float v = g_rv[li]; bi = g_ri[li];
#pragma unroll
            for (int s = 1; s < NSEG_RF; s++) {
                float vo = g_rv[s * MAXB + li];
                int   io = g_ri[s * MAXB + li];
                if (vo < v) { v = vo; bi = io; }
            }
        }
        if (txg == 0 && write_idx) out_idx[row] = (float)bi;
        const float4* cq = reinterpret_cast<const float4*>(codes + (size_t)bi * DDIM + txg * 8);
        float4 q0 = cq[0], q1 = cq[1];
        float4* od = reinterpret_cast<float4*>(out_q + (size_t)row * DDIM + txg * 8);
        od[0] = q0; od[1] = q1;
        const float4* xp = reinterpret_cast<const float4*>(x + (size_t)row * DDIM + txg * 8);
        float4 x0 = xp[0], x1 = xp[1];
        float d;
        d = x0.x - q0.x; thr_loss = fmaf(d, d, thr_loss);
        d = x0.y - q0.y; thr_loss = fmaf(d, d, thr_loss);
        d = x0.z - q0.z; thr_loss = fmaf(d, d, thr_loss);
        d = x0.w - q0.w; thr_loss = fmaf(d, d, thr_loss);
        d = x1.x - q1.x; thr_loss = fmaf(d, d, thr_loss);
        d = x1.y - q1.y; thr_loss = fmaf(d, d, thr_loss);
        d = x1.z - q1.z; thr_loss = fmaf(d, d, thr_loss);
        d = x1.w - q1.w; thr_loss = fmaf(d, d, thr_loss);
    }
    __shared__ float red[8];
#pragma unroll
    for (int o = 16; o; o >>= 1) thr_loss += __shfl_xor_sync(0xffffffffu, thr_loss, o);
    if ((tid & 31) == 0) red[tid >> 5] = thr_loss;
    __syncthreads();
    if (tid == 0) {
        float s = 0.0f;
#pragma unroll
        for (int w = 0; w < 8; w++) s += red[w];
        g_block_loss[blockIdx.x] = s;
    }
}

__global__ void finalize_kernel(float* __restrict__ out_loss, int nblocks, float invB)
{
    __shared__ float red[256];
    float s = 0.0f;
    for (int i = threadIdx.x; i < nblocks; i += 256) s += g_block_loss[i];
    red[threadIdx.x] = s;
    __syncthreads();
    for (int o = 128; o; o >>= 1) {
        if (threadIdx.x < o) red[threadIdx.x] += red[threadIdx.x + o];
        __syncthreads();
    }
    if (threadIdx.x == 0) *out_loss = 1.25f * red[0] * invB;  // (1 + BETA) * mean ||x-q||^2
}

extern "C" void kernel_launch(void* const* d_in, const int* in_sizes, int n_in,
                              void* d_out, int out_size)
{
    const float* x     = (const float*)d_in[0];
    const float* codes = (const float*)d_in[1];
    const int B = in_sizes[0] / DDIM;
    const int C = in_sizes[1] / DDIM;

    float* out      = (float*)d_out;
    float* out_q    = out;
    float* out_idx  = out + (size_t)B * DDIM;
    float* out_loss = out + (size_t)B * DDIM + B;

    const long long need_idx  = (long long)B * DDIM + B;
    const long long need_loss = need_idx + 1;
    const int write_idx  = ((long long)out_size >= need_idx)  ? 1 : 0;
    const int write_loss = ((long long)out_size >= need_loss) ? 1 : 0;

    (void)cudaFuncSetAttribute(vq_pass1,  cudaFuncAttributeMaxDynamicSharedMemorySize, SMEM_P1);
    (void)cudaFuncSetAttribute(vq_refine, cudaFuncAttributeMaxDynamicSharedMemorySize, SMEM_RF);

    split_x<<<B / 128, 256>>>(x);
    split_c<<<C / 8, 256>>>(codes);
    vq_pass1<<<(B / 128) * NSEG_P1, TPB_P1, SMEM_P1>>>(C);
    decide_kernel<<<B / 256, 256>>>();
    vq_refine<<<(B / 64) * NSEG_RF, TPB_RF, SMEM_RF>>>(x, C);
    gather_loss<<<B / 64, 256>>>(x, codes, out_q, out_idx, write_idx);
    if (write_loss)
        finalize_kernel<<<1, 256>>>(out_loss, B / 64, 1.0f / (float)B);
}